// round 8
// baseline (speedup 1.0000x reference)
#include <cuda_runtime.h>
#include <cuda_bf16.h>
#include <cstdint>
#include <math.h>

#define BB 4
#define LL 2048
#define DD 1024
#define HH 16
#define DKK 64
#define BH (BB*HH)        // 64
#define MROWS (BB*LL)     // 8192

#define SPAD 40           // smem row stride (bf16) for K=32 chunks (proj)
#define SPAD2 72          // smem row stride (bf16) for K=64 tiles

// pipelined-stage smem layout (proj): per stage
#define ST_AH 0
#define ST_AL 10240       // 128*40*2
#define ST_BH 20480
#define ST_BL 25600       // 64*40*2
#define STAGE_BYTES 30720
#define PIPE_SMEM (2*STAGE_BYTES)      // 61440

// scores smem layout: Q hi/lo + K hi/lo + fp32 stage + stats-reduce scratch
#define SC_QH 0
#define SC_QL 18432       // 128*72*2
#define SC_KH 36864
#define SC_KL 55296
#define SC_STG 73728      // 128*33*4 = 16896
#define SC_RED 90624      // float2[128][4] = 4096
#define SC_SMEM 94720

// wav smem layout: P hi/lo [128][72], V hi/lo [64][72], stats
#define WP_H 0
#define WP_L 18432
#define WV_H 36864
#define WV_L 46080
#define WSTAT 55296       // float2[128] = 1024
#define WAV_SMEM 56320

// ---------------- device scratch (allocation-free) ----------------
__device__ float g_q[(size_t)BH * LL * DKK];     // [bh][l][dk]
__device__ float g_k[(size_t)BH * LL * DKK];
__device__ float g_vt[(size_t)BH * DKK * LL];    // [bh][dk][l]  (V transposed)
__device__ float g_oc[(size_t)MROWS * DD];       // concat attention output
__device__ float2 g_part[(size_t)BH * LL * 16];  // per (row, kt-tile) softmax partials
__device__ float2 g_rowstats[(size_t)BH * LL];   // per row (max, 1/sum)
__device__ float g_attn_scratch[(size_t)BH * LL * LL]; // fallback

// ---------------- mma helpers ----------------
__device__ __forceinline__ uint32_t s32(const void* p) {
    return (uint32_t)__cvta_generic_to_shared(p);
}

#define LDSM_X4(R, a)                                                          \
    asm volatile("ldmatrix.sync.aligned.m8n8.x4.shared.b16 {%0,%1,%2,%3}, [%4];" \
        : "=r"((R)[0]), "=r"((R)[1]), "=r"((R)[2]), "=r"((R)[3]) : "r"(a))
#define LDSM_X2(R, a)                                                          \
    asm volatile("ldmatrix.sync.aligned.m8n8.x2.shared.b16 {%0,%1}, [%2];"     \
        : "=r"((R)[0]), "=r"((R)[1]) : "r"(a))

__device__ __forceinline__ void mma_bf16(float* c, const uint32_t* a, const uint32_t* b) {
    asm volatile(
        "mma.sync.aligned.m16n8k16.row.col.f32.bf16.bf16.f32 "
        "{%0,%1,%2,%3}, {%4,%5,%6,%7}, {%8,%9}, {%0,%1,%2,%3};"
        : "+f"(c[0]), "+f"(c[1]), "+f"(c[2]), "+f"(c[3])
        : "r"(a[0]), "r"(a[1]), "r"(a[2]), "r"(a[3]), "r"(b[0]), "r"(b[1]));
}

__device__ __forceinline__ void cvt_split(const float4& v, uint2& hv, uint2& lv) {
    __nv_bfloat16 h0 = __float2bfloat16(v.x), h1 = __float2bfloat16(v.y);
    __nv_bfloat16 h2 = __float2bfloat16(v.z), h3 = __float2bfloat16(v.w);
    __nv_bfloat16 l0 = __float2bfloat16(v.x - __bfloat162float(h0));
    __nv_bfloat16 l1 = __float2bfloat16(v.y - __bfloat162float(h1));
    __nv_bfloat16 l2 = __float2bfloat16(v.z - __bfloat162float(h2));
    __nv_bfloat16 l3 = __float2bfloat16(v.w - __bfloat162float(h3));
    hv.x = ((uint32_t)__bfloat16_as_ushort(h1) << 16) | __bfloat16_as_ushort(h0);
    hv.y = ((uint32_t)__bfloat16_as_ushort(h3) << 16) | __bfloat16_as_ushort(h2);
    lv.x = ((uint32_t)__bfloat16_as_ushort(l1) << 16) | __bfloat16_as_ushort(l0);
    lv.y = ((uint32_t)__bfloat16_as_ushort(l3) << 16) | __bfloat16_as_ushort(l2);
}

// ---- pipelined chunk helpers (proj): [rows x 32] fp32 (row stride ld) ----
template <int N4>
__device__ __forceinline__ void ldg_chunk(float4 (&r)[N4], const float* __restrict__ g,
                                          int ld, int tid) {
    #pragma unroll
    for (int i = 0; i < N4; i++) {
        const int u = tid + i * 256;
        const int row = u >> 3, c4 = (u & 7) << 2;
        r[i] = *(const float4*)(g + (size_t)row * ld + c4);
    }
}
template <int N4>
__device__ __forceinline__ void sts_chunk(const float4 (&v)[N4], __nv_bfloat16* shi,
                                          __nv_bfloat16* slo, int tid) {
    #pragma unroll
    for (int i = 0; i < N4; i++) {
        const int u = tid + i * 256;
        const int row = u >> 3, c4 = (u & 7) << 2;
        uint2 hv, lv; cvt_split(v[i], hv, lv);
        *(uint2*)(shi + row * SPAD + c4) = hv;
        *(uint2*)(slo + row * SPAD + c4) = lv;
    }
}

// [128 x 64] fp32 (row stride ld) -> split hi/lo bf16 smem (stride SPAD2)
__device__ __forceinline__ void load_split64(__nv_bfloat16* shi, __nv_bfloat16* slo,
                                             const float* __restrict__ g, int ld, int tid) {
    #pragma unroll
    for (int i = 0; i < 8; i++) {
        const int u = tid + i * 256;
        const int r = u >> 4, c4 = (u & 15) << 2;
        float4 v = *(const float4*)(g + (size_t)r * ld + c4);
        uint2 hv, lv; cvt_split(v, hv, lv);
        *(uint2*)(shi + r * SPAD2 + c4) = hv;
        *(uint2*)(slo + r * SPAD2 + c4) = lv;
    }
}

// K tile [128x64] register prefetch + split store (stride SPAD2)
__device__ __forceinline__ void ldg_k(float4 (&r)[8], const float* __restrict__ g, int tid) {
    #pragma unroll
    for (int i = 0; i < 8; i++) {
        const int u = tid + i * 256;
        r[i] = *(const float4*)(g + (size_t)(u >> 4) * DKK + ((u & 15) << 2));
    }
}
__device__ __forceinline__ void sts_k(const float4 (&v)[8], char* hi, char* lo, int tid) {
    #pragma unroll
    for (int i = 0; i < 8; i++) {
        const int u = tid + i * 256;
        const int r = u >> 4, c4 = (u & 15) << 2;
        uint2 hv, lv; cvt_split(v[i], hv, lv);
        *(uint2*)((__nv_bfloat16*)hi + r * SPAD2 + c4) = hv;
        *(uint2*)((__nv_bfloat16*)lo + r * SPAD2 + c4) = lv;
    }
}

// One K-chunk of split-bf16 3-pass MMA (AhBh + AhBl + AlBh).
template <int MT, int NT, int STRIDE, int KC>
__device__ __forceinline__ void block_mma(
    const __nv_bfloat16* sAh, const __nv_bfloat16* sAl,
    const __nv_bfloat16* sBh, const __nv_bfloat16* sBl,
    int a_row0, int b_row0, int lane, float (&acc)[MT][NT][4]) {
    #pragma unroll
    for (int kb = 0; kb < KC; kb += 16) {
        uint32_t ah[MT][4], al[MT][4], bh[NT][2], bl[NT][2];
        const int ar = a_row0 + (lane & 15);
        const int ac = kb + ((lane >> 4) << 3);
        #pragma unroll
        for (int i = 0; i < MT; i++) {
            LDSM_X4(ah[i], s32(sAh + (ar + i * 16) * STRIDE + ac));
            LDSM_X4(al[i], s32(sAl + (ar + i * 16) * STRIDE + ac));
        }
        const int br = b_row0 + (lane & 7);
        const int bc = kb + (((lane >> 3) & 1) << 3);
        #pragma unroll
        for (int j = 0; j < NT; j++) {
            LDSM_X2(bh[j], s32(sBh + (br + j * 8) * STRIDE + bc));
            LDSM_X2(bl[j], s32(sBl + (br + j * 8) * STRIDE + bc));
        }
        #pragma unroll
        for (int i = 0; i < MT; i++)
            #pragma unroll
            for (int j = 0; j < NT; j++) {
                mma_bf16(acc[i][j], ah[i], bh[j]);
                mma_bf16(acc[i][j], ah[i], bl[j]);
                mma_bf16(acc[i][j], al[i], bh[j]);
            }
    }
}

// Stage a 32-col accumulator group into fp32 smem [128][33].
template <int MT, int NT>
__device__ __forceinline__ void stage_group(float* stg, int warp_m, int col_base, int lane,
                                            float (&acc)[MT][NT][4], float scale) {
    const int r0 = warp_m * MT * 16 + (lane >> 2);
    const int c0 = (lane & 3) * 2;
    #pragma unroll
    for (int i = 0; i < MT; i++)
        #pragma unroll
        for (int j = 0; j < NT; j++) {
            float* p = stg + (size_t)(r0 + i * 16) * 33 + col_base + j * 8 + c0;
            p[0] = acc[i][j][0] * scale;
            p[1] = acc[i][j][1] * scale;
            p[8 * 33 + 0] = acc[i][j][2] * scale;
            p[8 * 33 + 1] = acc[i][j][3] * scale;
        }
}

// ================= projection GEMM: C = A @ W^T + bias (tile 128x64, pipelined) ====
template <int MODE>
__global__ void __launch_bounds__(256, 2)
gemm_proj(const float* __restrict__ A, const float* __restrict__ W,
          const float* __restrict__ bias, float* __restrict__ out) {
    extern __shared__ char sm[];
    const int tid = threadIdx.x, lane = tid & 31, wid = tid >> 5;
    const int warp_m = wid & 1, warp_n = wid >> 1;     // 2 x 4; warp tile 64x16
    const int m0 = blockIdx.y * 128, n0 = blockIdx.x * 64;

    const float* Ab = A + (size_t)m0 * DD;
    const float* Wb = W + (size_t)n0 * DD;

    float acc[4][2][4] = {};
    float4 ra[4], rb[2];

    ldg_chunk<4>(ra, Ab, DD, tid);
    ldg_chunk<2>(rb, Wb, DD, tid);
    {
        char* s0 = sm;
        sts_chunk<4>(ra, (__nv_bfloat16*)(s0 + ST_AH), (__nv_bfloat16*)(s0 + ST_AL), tid);
        sts_chunk<2>(rb, (__nv_bfloat16*)(s0 + ST_BH), (__nv_bfloat16*)(s0 + ST_BL), tid);
    }
    ldg_chunk<4>(ra, Ab + 32, DD, tid);
    ldg_chunk<2>(rb, Wb + 32, DD, tid);
    __syncthreads();

    const int NK = DD / 32;   // 32
    for (int k = 0; k < NK; k++) {
        char* cur = sm + (k & 1) * STAGE_BYTES;
        block_mma<4, 2, SPAD, 32>((__nv_bfloat16*)(cur + ST_AH), (__nv_bfloat16*)(cur + ST_AL),
                                  (__nv_bfloat16*)(cur + ST_BH), (__nv_bfloat16*)(cur + ST_BL),
                                  warp_m * 64, warp_n * 16, lane, acc);
        if (k + 1 < NK) {
            char* nxt = sm + ((k + 1) & 1) * STAGE_BYTES;
            sts_chunk<4>(ra, (__nv_bfloat16*)(nxt + ST_AH), (__nv_bfloat16*)(nxt + ST_AL), tid);
            sts_chunk<2>(rb, (__nv_bfloat16*)(nxt + ST_BH), (__nv_bfloat16*)(nxt + ST_BL), tid);
        }
        if (k + 2 < NK) {
            ldg_chunk<4>(ra, Ab + (k + 2) * 32, DD, tid);
            ldg_chunk<2>(rb, Wb + (k + 2) * 32, DD, tid);
        }
        __syncthreads();
    }

    float* stg = (float*)sm;
    const int b = m0 >> 11, l0 = m0 & (LL - 1);
    for (int g = 0; g < 2; g++) {
        if ((warp_n >> 1) == g)
            stage_group<4, 2>(stg, warp_m, (warp_n & 1) * 16, lane, acc, 1.0f);
        __syncthreads();
        const int n_base = n0 + g * 32;
        if (MODE == 1) {
            const int h = n_base >> 6, cc = n_base & 63;
            float* dst = out + ((size_t)(b * HH + h) * DKK + cc) * LL + l0;
            for (int u = tid; u < 1024; u += 256) {
                const int c = u >> 5, l4 = (u & 31) << 2;
                const float bv = bias[n_base + c];
                float4 v;
                v.x = stg[(size_t)(l4 + 0) * 33 + c] + bv;
                v.y = stg[(size_t)(l4 + 1) * 33 + c] + bv;
                v.z = stg[(size_t)(l4 + 2) * 33 + c] + bv;
                v.w = stg[(size_t)(l4 + 3) * 33 + c] + bv;
                *(float4*)(dst + (size_t)c * LL + l4) = v;
            }
        } else {
            for (int u = tid; u < 1024; u += 256) {
                const int r = u >> 3, c4 = (u & 7) << 2;
                float4 v;
                v.x = stg[(size_t)r * 33 + c4 + 0] + bias[n_base + c4 + 0];
                v.y = stg[(size_t)r * 33 + c4 + 1] + bias[n_base + c4 + 1];
                v.z = stg[(size_t)r * 33 + c4 + 2] + bias[n_base + c4 + 2];
                v.w = stg[(size_t)r * 33 + c4 + 3] + bias[n_base + c4 + 3];
                if (MODE == 0) {
                    const int h = n_base >> 6, cc = (n_base & 63) + c4;
                    *(float4*)(out + ((size_t)(b * HH + h) * LL + l0 + r) * DKK + cc) = v;
                } else {
                    *(float4*)(out + (size_t)(m0 + r) * DD + n_base + c4) = v;
                }
            }
        }
        __syncthreads();
    }
}

// ===== scores: strips of 4 kt-tiles; raw S out + per-tile softmax partials =====
__global__ void __launch_bounds__(256, 2)
scores_mma(const float* __restrict__ q, const float* __restrict__ k,
           float* __restrict__ attn, float2* __restrict__ part) {
    const int strip = blockIdx.x, qt = blockIdx.y, bhid = blockIdx.z;
    const int kt0 = strip * 4;
    const int q0 = qt * 128;
    extern __shared__ char sm[];
    const int tid = threadIdx.x, lane = tid & 31, wid = tid >> 5;
    const int warp_m = wid & 1, warp_n = wid >> 1;     // 2 x 4; warp tile 64x32

    float* attnb = attn + ((size_t)bhid * LL + q0) * LL;

    if (kt0 > qt) {
        const float4 z = make_float4(0.f, 0.f, 0.f, 0.f);
        for (int u = tid; u < 128 * 128; u += 256) {
            const int r = u >> 7, c4 = (u & 127) << 2;
            *(float4*)(attnb + (size_t)r * LL + kt0 * 128 + c4) = z;
        }
        return;
    }

    load_split64((__nv_bfloat16*)(sm + SC_QH), (__nv_bfloat16*)(sm + SC_QL),
                 q + ((size_t)bhid * LL + q0) * DKK, DKK, tid);
    float4 kbuf[8];
    ldg_k(kbuf, k + ((size_t)bhid * LL + kt0 * 128) * DKK, tid);
    __syncthreads();

    float* stg = (float*)(sm + SC_STG);
    float2* red = (float2*)(sm + SC_RED);
    const int rbase = warp_m * 64 + (lane >> 2);
    const int cbase = warp_n * 32 + (lane & 3) * 2;

    for (int kt = kt0; kt < kt0 + 4; kt++) {
        if (kt <= qt) {
            sts_k(kbuf, sm + SC_KH, sm + SC_KL, tid);
            __syncthreads();

            float acc[4][4][4] = {};
            block_mma<4, 4, SPAD2, 64>((__nv_bfloat16*)(sm + SC_QH), (__nv_bfloat16*)(sm + SC_QL),
                                       (__nv_bfloat16*)(sm + SC_KH), (__nv_bfloat16*)(sm + SC_KL),
                                       warp_m * 64, warp_n * 32, lane, acc);

            if (kt + 1 <= qt && kt + 1 < kt0 + 4)
                ldg_k(kbuf, k + ((size_t)bhid * LL + (kt + 1) * 128) * DKK, tid);

            // per-tile row softmax partials (m, l)
            const bool diag = (kt == qt);
            #pragma unroll
            for (int i = 0; i < 4; i++)
                #pragma unroll
                for (int p = 0; p < 2; p++) {
                    const int rloc = rbase + i * 16 + p * 8;
                    const int grow = q0 + rloc;
                    float sv[8];
                    float tmax = -1e30f;
                    #pragma unroll
                    for (int j = 0; j < 4; j++)
                        #pragma unroll
                        for (int kk = 0; kk < 2; kk++) {
                            const float s = acc[i][j][p * 2 + kk] * 0.125f;
                            const int cg = kt * 128 + cbase + j * 8 + kk;
                            sv[j * 2 + kk] = (!diag || cg <= grow) ? s : -1e30f;
                            tmax = fmaxf(tmax, sv[j * 2 + kk]);
                        }
                    float l = 0.f;
                    #pragma unroll
                    for (int e = 0; e < 8; e++) l += __expf(sv[e] - tmax);
                    #pragma unroll
                    for (int off = 1; off <= 2; off <<= 1) {
                        float m2 = __shfl_xor_sync(0xffffffffu, tmax, off);
                        float l2 = __shfl_xor_sync(0xffffffffu, l, off);
                        float mn = fmaxf(tmax, m2);
                        l = l * __expf(tmax - mn) + l2 * __expf(m2 - mn);
                        tmax = mn;
                    }
                    if ((lane & 3) == 0) red[rloc * 4 + warp_n] = make_float2(tmax, l);
                }
            __syncthreads();
            if (tid < 128) {
                float m = -1e30f, l = 0.f;
                #pragma unroll
                for (int w = 0; w < 4; w++) {
                    float2 v = red[tid * 4 + w];
                    float mn = fmaxf(m, v.x);
                    l = l * __expf(m - mn) + v.y * __expf(v.x - mn);
                    m = mn;
                }
                part[((size_t)bhid * LL + q0 + tid) * 16 + kt] = make_float2(m, l);
            }

            // raw S epilogue (scaled by 1/8)
            for (int g = 0; g < 4; g++) {
                if (warp_n == g) stage_group<4, 4>(stg, warp_m, 0, lane, acc, 0.125f);
                __syncthreads();
                for (int u = tid; u < 1024; u += 256) {
                    const int r = u >> 3, c4 = (u & 7) << 2;
                    float4 v = make_float4(stg[(size_t)r * 33 + c4 + 0], stg[(size_t)r * 33 + c4 + 1],
                                           stg[(size_t)r * 33 + c4 + 2], stg[(size_t)r * 33 + c4 + 3]);
                    *(float4*)(attnb + (size_t)r * LL + kt * 128 + g * 32 + c4) = v;
                }
                __syncthreads();
            }
        } else {
            const float4 z = make_float4(0.f, 0.f, 0.f, 0.f);
            for (int u = tid; u < 128 * 32; u += 256) {
                const int r = u >> 5, c4 = (u & 31) << 2;
                *(float4*)(attnb + (size_t)r * LL + kt * 128 + c4) = z;
            }
        }
    }
}

// ================= stats reduce: fold <=16 tile partials per row =================
__global__ void stats_reduce(const float2* __restrict__ part,
                             float2* __restrict__ rowstats) {
    const int idx = blockIdx.x * 256 + threadIdx.x;   // 131072
    const int row = idx & (LL - 1);
    const int ntiles = (row >> 7) + 1;
    const float2* p = part + (size_t)idx * 16;
    float m = -1e30f, l = 0.f;
    for (int t = 0; t < ntiles; t++) {
        float2 v = p[t];
        float mn = fmaxf(m, v.x);
        l = l * __expf(m - mn) + v.y * __expf(v.x - mn);
        m = mn;
    }
    rowstats[idx] = make_float2(m, 1.0f / l);
}

// ===== wav: read raw S, write normalized W, accumulate O = W.V (K=64 chunks) =====
__global__ void __launch_bounds__(256, 2)
wav_mma(float* __restrict__ attn, const float* __restrict__ vt,
        const float2* __restrict__ rowstats, float* __restrict__ oc) {
    const int qt = (gridDim.x - 1) - blockIdx.x;   // heavy blocks first
    const int bhid = blockIdx.y;
    const int b = bhid >> 4, h = bhid & 15;
    extern __shared__ char sm[];
    const int tid = threadIdx.x, lane = tid & 31, wid = tid >> 5;
    const int warp_m = wid & 1, warp_n = wid >> 1;   // 2 x 4; warp tile 64x16
    const int q0 = qt * 128;

    float* attnb = attn + ((size_t)bhid * LL + q0) * LL;
    const float* vtb = vt + (size_t)bhid * DKK * LL;
    float2* sstat = (float2*)(sm + WSTAT);

    if (tid < 128) sstat[tid] = rowstats[(size_t)bhid * LL + q0 + tid];
    __syncthreads();

    float oacc[4][2][4] = {};
    const int nch = (qt + 1) * 2;   // K=64 chunks

    for (int ch = 0; ch < nch; ch++) {
        const int c0 = ch * 64;
        // S chunk [128 x 64]: w = exp(s - m) * invl (diag-masked), write W, split to P
        #pragma unroll
        for (int i = 0; i < 8; i++) {
            const int u = tid + i * 256;
            const int r = u >> 4, c4 = (u & 15) << 2;
            float* gp = attnb + (size_t)r * LL + c0 + c4;
            float4 s = *(const float4*)gp;
            const float2 st = sstat[r];
            const int grow = q0 + r, cg = c0 + c4;
            float4 w;
            w.x = (cg + 0 <= grow) ? __expf(s.x - st.x) * st.y : 0.f;
            w.y = (cg + 1 <= grow) ? __expf(s.y - st.x) * st.y : 0.f;
            w.z = (cg + 2 <= grow) ? __expf(s.z - st.x) * st.y : 0.f;
            w.w = (cg + 3 <= grow) ? __expf(s.w - st.x) * st.y : 0.f;
            *(float4*)gp = w;
            uint2 hv, lv; cvt_split(w, hv, lv);
            *(uint2*)((__nv_bfloat16*)(sm + WP_H) + r * SPAD2 + c4) = hv;
            *(uint2*)((__nv_bfloat16*)(sm + WP_L) + r * SPAD2 + c4) = lv;
        }
        // V chunk [64 x 64]
        #pragma unroll
        for (int i = 0; i < 4; i++) {
            const int u = tid + i * 256;
            const int r = u >> 4, c4 = (u & 15) << 2;
            float4 v = *(const float4*)(vtb + (size_t)r * LL + c0 + c4);
            uint2 hv, lv; cvt_split(v, hv, lv);
            *(uint2*)((__nv_bfloat16*)(sm + WV_H) + r * SPAD2 + c4) = hv;
            *(uint2*)((__nv_bfloat16*)(sm + WV_L) + r * SPAD2 + c4) = lv;
        }
        __syncthreads();
        block_mma<4, 2, SPAD2, 64>((__nv_bfloat16*)(sm + WP_H), (__nv_bfloat16*)(sm + WP_L),
                                   (__nv_bfloat16*)(sm + WV_H), (__nv_bfloat16*)(sm + WV_L),
                                   warp_m * 64, warp_n * 16, lane, oacc);
        __syncthreads();
    }

    // O epilogue -> concat layout (reuse P region as fp32 stage)
    float* stg = (float*)sm;
    for (int g = 0; g < 2; g++) {
        if ((warp_n >> 1) == g)
            stage_group<4, 2>(stg, warp_m, (warp_n & 1) * 16, lane, oacc, 1.0f);
        __syncthreads();
        for (int u = tid; u < 1024; u += 256) {
            const int r = u >> 3, c4 = (u & 7) << 2;
            float4 v = make_float4(stg[(size_t)r * 33 + c4 + 0], stg[(size_t)r * 33 + c4 + 1],
                                   stg[(size_t)r * 33 + c4 + 2], stg[(size_t)r * 33 + c4 + 3]);
            *(float4*)(oc + (size_t)(b * LL + q0 + r) * DD + h * DKK + g * 32 + c4) = v;
        }
        __syncthreads();
    }
}

// ---------------- launch ----------------
extern "C" void kernel_launch(void* const* d_in, const int* in_sizes, int n_in,
                              void* d_out, int out_size) {
    const float* x  = (const float*)d_in[0];
    const float* Wq = (const float*)d_in[2];
    const float* bq = (const float*)d_in[3];
    const float* Wk = (const float*)d_in[4];
    const float* bk = (const float*)d_in[5];
    const float* Wv = (const float*)d_in[6];
    const float* bv = (const float*)d_in[7];
    const float* Wo = (const float*)d_in[8];
    const float* bo = (const float*)d_in[9];
    float* out = (float*)d_out;

    const size_t out_elems  = (size_t)BB * LL * DD;
    const size_t attn_elems = (size_t)BH * LL * LL;

    float *q, *k, *vt, *oc, *attn;
    float2 *part, *rowstats;
    cudaGetSymbolAddress((void**)&q,  g_q);
    cudaGetSymbolAddress((void**)&k,  g_k);
    cudaGetSymbolAddress((void**)&vt, g_vt);
    cudaGetSymbolAddress((void**)&oc, g_oc);
    cudaGetSymbolAddress((void**)&part, g_part);
    cudaGetSymbolAddress((void**)&rowstats, g_rowstats);
    if ((size_t)out_size >= out_elems + attn_elems) {
        attn = out + out_elems;
    } else {
        cudaGetSymbolAddress((void**)&attn, g_attn_scratch);
    }

    cudaFuncSetAttribute(gemm_proj<0>, cudaFuncAttributeMaxDynamicSharedMemorySize, PIPE_SMEM);
    cudaFuncSetAttribute(gemm_proj<1>, cudaFuncAttributeMaxDynamicSharedMemorySize, PIPE_SMEM);
    cudaFuncSetAttribute(gemm_proj<2>, cudaFuncAttributeMaxDynamicSharedMemorySize, PIPE_SMEM);
    cudaFuncSetAttribute(scores_mma,   cudaFuncAttributeMaxDynamicSharedMemorySize, SC_SMEM);
    cudaFuncSetAttribute(wav_mma,      cudaFuncAttributeMaxDynamicSharedMemorySize, WAV_SMEM);

    dim3 projGrid(DD / 64, MROWS / 128);       // (16, 64)
    gemm_proj<0><<<projGrid, 256, PIPE_SMEM>>>(x, Wq, bq, q);
    gemm_proj<0><<<projGrid, 256, PIPE_SMEM>>>(x, Wk, bk, k);
    gemm_proj<1><<<projGrid, 256, PIPE_SMEM>>>(x, Wv, bv, vt);

    dim3 scoreGrid(4, LL / 128, BH);           // (4, 16, 64)
    scores_mma<<<scoreGrid, 256, SC_SMEM>>>(q, k, attn, part);

    stats_reduce<<<(BH * LL) / 256, 256>>>(part, rowstats);

    dim3 wavGrid(LL / 128, BH);                // (16, 64)
    wav_mma<<<wavGrid, 256, WAV_SMEM>>>(attn, vt, rowstats, oc);

    gemm_proj<2><<<projGrid, 256, PIPE_SMEM>>>(oc, Wo, bo, out);
}

// round 10
// speedup vs baseline: 1.1885x; 1.1885x over previous
#include <cuda_runtime.h>
#include <cuda_bf16.h>
#include <cstdint>
#include <math.h>

#define BB 4
#define LL 2048
#define DD 1024
#define HH 16
#define DKK 64
#define BH (BB*HH)        // 64
#define MROWS (BB*LL)     // 8192

#define SPAD 40           // smem row stride (bf16) for K=32 chunks
#define SPAD2 72          // smem row stride (bf16) for K=64 tiles (scores)

// pipelined-stage smem layout (proj / av): per stage
#define ST_AH 0
#define ST_AL 10240       // 128*40*2
#define ST_BH 20480
#define ST_BL 25600       // 64*40*2
#define STAGE_BYTES 30720
#define PIPE_SMEM (2*STAGE_BYTES)      // 61440

// scores smem layout: Q hi/lo + K hi/lo (no fp32 stage needed)
#define SC_QH 0
#define SC_QL 18432       // 128*72*2
#define SC_KH 36864
#define SC_KL 55296
#define SC_SMEM 73728

// ---------------- device scratch (allocation-free) ----------------
__device__ float g_q[(size_t)BH * LL * DKK];     // [bh][l][dk]
__device__ float g_k[(size_t)BH * LL * DKK];
__device__ float g_vt[(size_t)BH * DKK * LL];    // [bh][dk][l]  (V transposed)
__device__ float g_oc[(size_t)MROWS * DD];       // concat attention output
__device__ float g_attn_scratch[(size_t)BH * LL * LL]; // fallback

// ---------------- mma helpers ----------------
__device__ __forceinline__ uint32_t s32(const void* p) {
    return (uint32_t)__cvta_generic_to_shared(p);
}

#define LDSM_X4(R, a)                                                          \
    asm volatile("ldmatrix.sync.aligned.m8n8.x4.shared.b16 {%0,%1,%2,%3}, [%4];" \
        : "=r"((R)[0]), "=r"((R)[1]), "=r"((R)[2]), "=r"((R)[3]) : "r"(a))
#define LDSM_X2(R, a)                                                          \
    asm volatile("ldmatrix.sync.aligned.m8n8.x2.shared.b16 {%0,%1}, [%2];"     \
        : "=r"((R)[0]), "=r"((R)[1]) : "r"(a))

__device__ __forceinline__ void mma_bf16(float* c, const uint32_t* a, const uint32_t* b) {
    asm volatile(
        "mma.sync.aligned.m16n8k16.row.col.f32.bf16.bf16.f32 "
        "{%0,%1,%2,%3}, {%4,%5,%6,%7}, {%8,%9}, {%0,%1,%2,%3};"
        : "+f"(c[0]), "+f"(c[1]), "+f"(c[2]), "+f"(c[3])
        : "r"(a[0]), "r"(a[1]), "r"(a[2]), "r"(a[3]), "r"(b[0]), "r"(b[1]));
}

__device__ __forceinline__ void cvt_split(const float4& v, uint2& hv, uint2& lv) {
    __nv_bfloat16 h0 = __float2bfloat16(v.x), h1 = __float2bfloat16(v.y);
    __nv_bfloat16 h2 = __float2bfloat16(v.z), h3 = __float2bfloat16(v.w);
    __nv_bfloat16 l0 = __float2bfloat16(v.x - __bfloat162float(h0));
    __nv_bfloat16 l1 = __float2bfloat16(v.y - __bfloat162float(h1));
    __nv_bfloat16 l2 = __float2bfloat16(v.z - __bfloat162float(h2));
    __nv_bfloat16 l3 = __float2bfloat16(v.w - __bfloat162float(h3));
    hv.x = ((uint32_t)__bfloat16_as_ushort(h1) << 16) | __bfloat16_as_ushort(h0);
    hv.y = ((uint32_t)__bfloat16_as_ushort(h3) << 16) | __bfloat16_as_ushort(h2);
    lv.x = ((uint32_t)__bfloat16_as_ushort(l1) << 16) | __bfloat16_as_ushort(l0);
    lv.y = ((uint32_t)__bfloat16_as_ushort(l3) << 16) | __bfloat16_as_ushort(l2);
}

// ---- pipelined chunk helpers: [rows x 32] fp32 (row stride ld) ----
template <int N4>
__device__ __forceinline__ void ldg_chunk(float4 (&r)[N4], const float* __restrict__ g,
                                          int ld, int tid) {
    #pragma unroll
    for (int i = 0; i < N4; i++) {
        const int u = tid + i * 256;
        const int row = u >> 3, c4 = (u & 7) << 2;
        r[i] = *(const float4*)(g + (size_t)row * ld + c4);
    }
}
template <int N4>
__device__ __forceinline__ void sts_chunk(const float4 (&v)[N4], __nv_bfloat16* shi,
                                          __nv_bfloat16* slo, int tid) {
    #pragma unroll
    for (int i = 0; i < N4; i++) {
        const int u = tid + i * 256;
        const int row = u >> 3, c4 = (u & 7) << 2;
        uint2 hv, lv; cvt_split(v[i], hv, lv);
        *(uint2*)(shi + row * SPAD + c4) = hv;
        *(uint2*)(slo + row * SPAD + c4) = lv;
    }
}

// [128 x 64] fp32 (row stride ld) -> split hi/lo bf16 smem (stride SPAD2)
__device__ __forceinline__ void load_split64(__nv_bfloat16* shi, __nv_bfloat16* slo,
                                             const float* __restrict__ g, int ld, int tid) {
    #pragma unroll
    for (int i = 0; i < 8; i++) {
        const int u = tid + i * 256;
        const int r = u >> 4, c4 = (u & 15) << 2;
        float4 v = *(const float4*)(g + (size_t)r * ld + c4);
        uint2 hv, lv; cvt_split(v, hv, lv);
        *(uint2*)(shi + r * SPAD2 + c4) = hv;
        *(uint2*)(slo + r * SPAD2 + c4) = lv;
    }
}

// One K-chunk of split-bf16 3-pass MMA (AhBh + AhBl + AlBh).
template <int MT, int NT, int STRIDE, int KC>
__device__ __forceinline__ void block_mma(
    const __nv_bfloat16* sAh, const __nv_bfloat16* sAl,
    const __nv_bfloat16* sBh, const __nv_bfloat16* sBl,
    int a_row0, int b_row0, int lane, float (&acc)[MT][NT][4]) {
    #pragma unroll
    for (int kb = 0; kb < KC; kb += 16) {
        uint32_t ah[MT][4], al[MT][4], bh[NT][2], bl[NT][2];
        const int ar = a_row0 + (lane & 15);
        const int ac = kb + ((lane >> 4) << 3);
        #pragma unroll
        for (int i = 0; i < MT; i++) {
            LDSM_X4(ah[i], s32(sAh + (ar + i * 16) * STRIDE + ac));
            LDSM_X4(al[i], s32(sAl + (ar + i * 16) * STRIDE + ac));
        }
        const int br = b_row0 + (lane & 7);
        const int bc = kb + (((lane >> 3) & 1) << 3);
        #pragma unroll
        for (int j = 0; j < NT; j++) {
            LDSM_X2(bh[j], s32(sBh + (br + j * 8) * STRIDE + bc));
            LDSM_X2(bl[j], s32(sBl + (br + j * 8) * STRIDE + bc));
        }
        #pragma unroll
        for (int i = 0; i < MT; i++)
            #pragma unroll
            for (int j = 0; j < NT; j++) {
                mma_bf16(acc[i][j], ah[i], bh[j]);
                mma_bf16(acc[i][j], ah[i], bl[j]);
                mma_bf16(acc[i][j], al[i], bh[j]);
            }
    }
}

// Stage a 32-col accumulator group into fp32 smem [128][33] (proj epilogue only).
template <int MT, int NT>
__device__ __forceinline__ void stage_group(float* stg, int warp_m, int col_base, int lane,
                                            float (&acc)[MT][NT][4], float scale) {
    const int r0 = warp_m * MT * 16 + (lane >> 2);
    const int c0 = (lane & 3) * 2;
    #pragma unroll
    for (int i = 0; i < MT; i++)
        #pragma unroll
        for (int j = 0; j < NT; j++) {
            float* p = stg + (size_t)(r0 + i * 16) * 33 + col_base + j * 8 + c0;
            p[0] = acc[i][j][0] * scale;
            p[1] = acc[i][j][1] * scale;
            p[8 * 33 + 0] = acc[i][j][2] * scale;
            p[8 * 33 + 1] = acc[i][j][3] * scale;
        }
}

// ================= projection GEMM: C = A @ W^T + bias (tile 128x64, pipelined) ====
template <int MODE>
__global__ void __launch_bounds__(256, 2)
gemm_proj(const float* __restrict__ A, const float* __restrict__ W,
          const float* __restrict__ bias, float* __restrict__ out) {
    extern __shared__ char sm[];
    const int tid = threadIdx.x, lane = tid & 31, wid = tid >> 5;
    const int warp_m = wid & 1, warp_n = wid >> 1;     // 2 x 4; warp tile 64x16
    const int m0 = blockIdx.y * 128, n0 = blockIdx.x * 64;

    const float* Ab = A + (size_t)m0 * DD;
    const float* Wb = W + (size_t)n0 * DD;

    float acc[4][2][4] = {};
    float4 ra[4], rb[2];

    ldg_chunk<4>(ra, Ab, DD, tid);
    ldg_chunk<2>(rb, Wb, DD, tid);
    {
        char* s0 = sm;
        sts_chunk<4>(ra, (__nv_bfloat16*)(s0 + ST_AH), (__nv_bfloat16*)(s0 + ST_AL), tid);
        sts_chunk<2>(rb, (__nv_bfloat16*)(s0 + ST_BH), (__nv_bfloat16*)(s0 + ST_BL), tid);
    }
    ldg_chunk<4>(ra, Ab + 32, DD, tid);
    ldg_chunk<2>(rb, Wb + 32, DD, tid);
    __syncthreads();

    const int NK = DD / 32;   // 32
    for (int k = 0; k < NK; k++) {
        char* cur = sm + (k & 1) * STAGE_BYTES;
        block_mma<4, 2, SPAD, 32>((__nv_bfloat16*)(cur + ST_AH), (__nv_bfloat16*)(cur + ST_AL),
                                  (__nv_bfloat16*)(cur + ST_BH), (__nv_bfloat16*)(cur + ST_BL),
                                  warp_m * 64, warp_n * 16, lane, acc);
        if (k + 1 < NK) {
            char* nxt = sm + ((k + 1) & 1) * STAGE_BYTES;
            sts_chunk<4>(ra, (__nv_bfloat16*)(nxt + ST_AH), (__nv_bfloat16*)(nxt + ST_AL), tid);
            sts_chunk<2>(rb, (__nv_bfloat16*)(nxt + ST_BH), (__nv_bfloat16*)(nxt + ST_BL), tid);
        }
        if (k + 2 < NK) {
            ldg_chunk<4>(ra, Ab + (k + 2) * 32, DD, tid);
            ldg_chunk<2>(rb, Wb + (k + 2) * 32, DD, tid);
        }
        __syncthreads();
    }

    float* stg = (float*)sm;
    const int b = m0 >> 11, l0 = m0 & (LL - 1);
    for (int g = 0; g < 2; g++) {
        if ((warp_n >> 1) == g)
            stage_group<4, 2>(stg, warp_m, (warp_n & 1) * 16, lane, acc, 1.0f);
        __syncthreads();
        const int n_base = n0 + g * 32;
        if (MODE == 1) {
            const int h = n_base >> 6, cc = n_base & 63;
            float* dst = out + ((size_t)(b * HH + h) * DKK + cc) * LL + l0;
            for (int u = tid; u < 1024; u += 256) {
                const int c = u >> 5, l4 = (u & 31) << 2;
                const float bv = bias[n_base + c];
                float4 v;
                v.x = stg[(size_t)(l4 + 0) * 33 + c] + bv;
                v.y = stg[(size_t)(l4 + 1) * 33 + c] + bv;
                v.z = stg[(size_t)(l4 + 2) * 33 + c] + bv;
                v.w = stg[(size_t)(l4 + 3) * 33 + c] + bv;
                *(float4*)(dst + (size_t)c * LL + l4) = v;
            }
        } else {
            for (int u = tid; u < 1024; u += 256) {
                const int r = u >> 3, c4 = (u & 7) << 2;
                float4 v;
                v.x = stg[(size_t)r * 33 + c4 + 0] + bias[n_base + c4 + 0];
                v.y = stg[(size_t)r * 33 + c4 + 1] + bias[n_base + c4 + 1];
                v.z = stg[(size_t)r * 33 + c4 + 2] + bias[n_base + c4 + 2];
                v.w = stg[(size_t)r * 33 + c4 + 3] + bias[n_base + c4 + 3];
                if (MODE == 0) {
                    const int h = n_base >> 6, cc = (n_base & 63) + c4;
                    *(float4*)(out + ((size_t)(b * HH + h) * LL + l0 + r) * DKK + cc) = v;
                } else {
                    *(float4*)(out + (size_t)(m0 + r) * DD + n_base + c4) = v;
                }
            }
        }
        __syncthreads();
    }
}

// ===== scores: strips of 4 kt-tiles; Q loaded once; direct STG.64 epilogue =====
__global__ void __launch_bounds__(256, 2)
scores_mma(const float* __restrict__ q, const float* __restrict__ k,
           float* __restrict__ attn) {
    const int strip = blockIdx.x, qt = blockIdx.y, bhid = blockIdx.z;
    const int kt0 = strip * 4;
    const int q0 = qt * 128;
    extern __shared__ char sm[];
    const int tid = threadIdx.x, lane = tid & 31, wid = tid >> 5;
    const int warp_m = wid & 1, warp_n = wid >> 1;     // 2 x 4; warp tile 64x32

    float* attnb = attn + ((size_t)bhid * LL + q0) * LL;

    if (kt0 > qt) {
        const float4 z = make_float4(0.f, 0.f, 0.f, 0.f);
        for (int u = tid; u < 128 * 128; u += 256) {
            const int r = u >> 7, c4 = (u & 127) << 2;
            *(float4*)(attnb + (size_t)r * LL + kt0 * 128 + c4) = z;
        }
        return;
    }

    load_split64((__nv_bfloat16*)(sm + SC_QH), (__nv_bfloat16*)(sm + SC_QL),
                 q + ((size_t)bhid * LL + q0) * DKK, DKK, tid);
    float4 kbuf[8];
    {
        const float* kb = k + ((size_t)bhid * LL + kt0 * 128) * DKK;
        #pragma unroll
        for (int i = 0; i < 8; i++) {
            const int u = tid + i * 256;
            kbuf[i] = *(const float4*)(kb + (size_t)(u >> 4) * DKK + ((u & 15) << 2));
        }
    }
    __syncthreads();

    const int rbase = warp_m * 64 + (lane >> 2);
    const int cbase = warp_n * 32 + (lane & 3) * 2;

    for (int kt = kt0; kt < kt0 + 4; kt++) {
        if (kt <= qt) {
            #pragma unroll
            for (int i = 0; i < 8; i++) {
                const int u = tid + i * 256;
                const int r = u >> 4, c4 = (u & 15) << 2;
                uint2 hv, lv; cvt_split(kbuf[i], hv, lv);
                *(uint2*)((__nv_bfloat16*)(sm + SC_KH) + r * SPAD2 + c4) = hv;
                *(uint2*)((__nv_bfloat16*)(sm + SC_KL) + r * SPAD2 + c4) = lv;
            }
            __syncthreads();

            float acc[4][4][4] = {};
            block_mma<4, 4, SPAD2, 64>((__nv_bfloat16*)(sm + SC_QH), (__nv_bfloat16*)(sm + SC_QL),
                                       (__nv_bfloat16*)(sm + SC_KH), (__nv_bfloat16*)(sm + SC_KL),
                                       warp_m * 64, warp_n * 32, lane, acc);

            // prefetch next K during epilogue
            if (kt + 1 <= qt && kt + 1 < kt0 + 4) {
                const float* kb = k + ((size_t)bhid * LL + (kt + 1) * 128) * DKK;
                #pragma unroll
                for (int i = 0; i < 8; i++) {
                    const int u = tid + i * 256;
                    kbuf[i] = *(const float4*)(kb + (size_t)(u >> 4) * DKK + ((u & 15) << 2));
                }
            }

            // direct STG.64 epilogue: no barriers, no smem round-trip
            #pragma unroll
            for (int i = 0; i < 4; i++)
                #pragma unroll
                for (int p = 0; p < 2; p++) {
                    const int r = rbase + i * 16 + p * 8;
                    float* rowp = attnb + (size_t)r * LL + kt * 128 + cbase;
                    #pragma unroll
                    for (int j = 0; j < 4; j++) {
                        float2 v = make_float2(acc[i][j][p * 2] * 0.125f,
                                               acc[i][j][p * 2 + 1] * 0.125f);
                        *(float2*)(rowp + j * 8) = v;
                    }
                }
            __syncthreads();   // K buffer reuse guard
        } else {
            const float4 z = make_float4(0.f, 0.f, 0.f, 0.f);
            for (int u = tid; u < 128 * 32; u += 256) {
                const int r = u >> 5, c4 = (u & 31) << 2;
                *(float4*)(attnb + (size_t)r * LL + kt * 128 + c4) = z;
            }
        }
    }
}

// ================= O = P @ V (causal k-range, pipelined, direct epilogue) ==========
__global__ void __launch_bounds__(256, 2)
av_mma(const float* __restrict__ attn, const float* __restrict__ vt,
       float* __restrict__ oc) {
    const int qt = blockIdx.x, bhid = blockIdx.y;
    const int b = bhid >> 4, h = bhid & 15;
    extern __shared__ char sm[];
    const int tid = threadIdx.x, lane = tid & 31, wid = tid >> 5;
    const int warp_m = wid & 1, warp_n = wid >> 1;
    const int q0 = qt * 128;

    const float* Pb = attn + ((size_t)bhid * LL + q0) * LL;
    const float* Vb = vt + (size_t)bhid * DKK * LL;

    float acc[4][2][4] = {};
    float4 ra[4], rb[2];

    const int NK = (qt + 1) * 4;

    ldg_chunk<4>(ra, Pb, LL, tid);
    ldg_chunk<2>(rb, Vb, LL, tid);
    {
        char* s0 = sm;
        sts_chunk<4>(ra, (__nv_bfloat16*)(s0 + ST_AH), (__nv_bfloat16*)(s0 + ST_AL), tid);
        sts_chunk<2>(rb, (__nv_bfloat16*)(s0 + ST_BH), (__nv_bfloat16*)(s0 + ST_BL), tid);
    }
    ldg_chunk<4>(ra, Pb + 32, LL, tid);
    ldg_chunk<2>(rb, Vb + 32, LL, tid);
    __syncthreads();

    for (int k = 0; k < NK; k++) {
        char* cur = sm + (k & 1) * STAGE_BYTES;
        block_mma<4, 2, SPAD, 32>((__nv_bfloat16*)(cur + ST_AH), (__nv_bfloat16*)(cur + ST_AL),
                                  (__nv_bfloat16*)(cur + ST_BH), (__nv_bfloat16*)(cur + ST_BL),
                                  warp_m * 64, warp_n * 16, lane, acc);
        if (k + 1 < NK) {
            char* nxt = sm + ((k + 1) & 1) * STAGE_BYTES;
            sts_chunk<4>(ra, (__nv_bfloat16*)(nxt + ST_AH), (__nv_bfloat16*)(nxt + ST_AL), tid);
            sts_chunk<2>(rb, (__nv_bfloat16*)(nxt + ST_BH), (__nv_bfloat16*)(nxt + ST_BL), tid);
        }
        if (k + 2 < NK) {
            ldg_chunk<4>(ra, Pb + (k + 2) * 32, LL, tid);
            ldg_chunk<2>(rb, Vb + (k + 2) * 32, LL, tid);
        }
        __syncthreads();
    }

    // direct STG.64 epilogue to concat layout
    const int rbase = warp_m * 64 + (lane >> 2);
    const int cbase = warp_n * 16 + (lane & 3) * 2;
    #pragma unroll
    for (int i = 0; i < 4; i++)
        #pragma unroll
        for (int p = 0; p < 2; p++) {
            const int r = rbase + i * 16 + p * 8;
            float* rowp = oc + (size_t)(b * LL + q0 + r) * DD + h * DKK + cbase;
            #pragma unroll
            for (int j = 0; j < 2; j++) {
                float2 v = make_float2(acc[i][j][p * 2], acc[i][j][p * 2 + 1]);
                *(float2*)(rowp + j * 8) = v;
            }
        }
}

// ================= row softmax (causal, bounded to qt-tile-aligned end) ============
__global__ void softmax_kernel(float* __restrict__ attn) {
    const int row = blockIdx.x, bh = blockIdx.y;
    float* p = attn + ((size_t)bh * LL + row) * LL;
    const int valid = row + 1;
    const int nend = (((row >> 7) + 1) << 7);   // 128..2048, zeros beyond pre-written
    const int tid = threadIdx.x;

    __shared__ float sred[8];

    float4 v[2];
    float m = -3.4e38f;
    #pragma unroll
    for (int i = 0; i < 2; i++) {
        const int j = (tid + i * 256) * 4;
        if (j < nend) {
            v[i] = *(const float4*)(p + j);
            if (j + 0 < valid) m = fmaxf(m, v[i].x);
            if (j + 1 < valid) m = fmaxf(m, v[i].y);
            if (j + 2 < valid) m = fmaxf(m, v[i].z);
            if (j + 3 < valid) m = fmaxf(m, v[i].w);
        }
    }
    #pragma unroll
    for (int o = 16; o > 0; o >>= 1) m = fmaxf(m, __shfl_xor_sync(0xffffffff, m, o));
    if ((tid & 31) == 0) sred[tid >> 5] = m;
    __syncthreads();
    m = sred[0];
    #pragma unroll
    for (int w = 1; w < 8; w++) m = fmaxf(m, sred[w]);

    float sum = 0.0f;
    #pragma unroll
    for (int i = 0; i < 2; i++) {
        const int j = (tid + i * 256) * 4;
        if (j < nend) {
            v[i].x = (j + 0 < valid) ? __expf(v[i].x - m) : 0.0f;
            v[i].y = (j + 1 < valid) ? __expf(v[i].y - m) : 0.0f;
            v[i].z = (j + 2 < valid) ? __expf(v[i].z - m) : 0.0f;
            v[i].w = (j + 3 < valid) ? __expf(v[i].w - m) : 0.0f;
            sum += v[i].x + v[i].y + v[i].z + v[i].w;
        }
    }
    __syncthreads();
    #pragma unroll
    for (int o = 16; o > 0; o >>= 1) sum += __shfl_xor_sync(0xffffffff, sum, o);
    if ((tid & 31) == 0) sred[tid >> 5] = sum;
    __syncthreads();
    sum = 0.0f;
    #pragma unroll
    for (int w = 0; w < 8; w++) sum += sred[w];
    const float inv = 1.0f / sum;

    #pragma unroll
    for (int i = 0; i < 2; i++) {
        const int j = (tid + i * 256) * 4;
        if (j < nend) {
            float4 o4;
            o4.x = v[i].x * inv; o4.y = v[i].y * inv;
            o4.z = v[i].z * inv; o4.w = v[i].w * inv;
            *(float4*)(p + j) = o4;
        }
    }
}

// ---------------- launch ----------------
extern "C" void kernel_launch(void* const* d_in, const int* in_sizes, int n_in,
                              void* d_out, int out_size) {
    const float* x  = (const float*)d_in[0];
    const float* Wq = (const float*)d_in[2];
    const float* bq = (const float*)d_in[3];
    const float* Wk = (const float*)d_in[4];
    const float* bk = (const float*)d_in[5];
    const float* Wv = (const float*)d_in[6];
    const float* bv = (const float*)d_in[7];
    const float* Wo = (const float*)d_in[8];
    const float* bo = (const float*)d_in[9];
    float* out = (float*)d_out;

    const size_t out_elems  = (size_t)BB * LL * DD;
    const size_t attn_elems = (size_t)BH * LL * LL;

    float *q, *k, *vt, *oc, *attn;
    cudaGetSymbolAddress((void**)&q,  g_q);
    cudaGetSymbolAddress((void**)&k,  g_k);
    cudaGetSymbolAddress((void**)&vt, g_vt);
    cudaGetSymbolAddress((void**)&oc, g_oc);
    if ((size_t)out_size >= out_elems + attn_elems) {
        attn = out + out_elems;
    } else {
        cudaGetSymbolAddress((void**)&attn, g_attn_scratch);
    }

    cudaFuncSetAttribute(gemm_proj<0>, cudaFuncAttributeMaxDynamicSharedMemorySize, PIPE_SMEM);
    cudaFuncSetAttribute(gemm_proj<1>, cudaFuncAttributeMaxDynamicSharedMemorySize, PIPE_SMEM);
    cudaFuncSetAttribute(gemm_proj<2>, cudaFuncAttributeMaxDynamicSharedMemorySize, PIPE_SMEM);
    cudaFuncSetAttribute(scores_mma,   cudaFuncAttributeMaxDynamicSharedMemorySize, SC_SMEM);
    cudaFuncSetAttribute(av_mma,       cudaFuncAttributeMaxDynamicSharedMemorySize, PIPE_SMEM);

    dim3 projGrid(DD / 64, MROWS / 128);       // (16, 64)
    gemm_proj<0><<<projGrid, 256, PIPE_SMEM>>>(x, Wq, bq, q);
    gemm_proj<0><<<projGrid, 256, PIPE_SMEM>>>(x, Wk, bk, k);
    gemm_proj<1><<<projGrid, 256, PIPE_SMEM>>>(x, Wv, bv, vt);

    dim3 scoreGrid(4, LL / 128, BH);           // (4, 16, 64)
    scores_mma<<<scoreGrid, 256, SC_SMEM>>>(q, k, attn);

    dim3 smGrid(LL, BH);
    softmax_kernel<<<smGrid, 256>>>(attn);

    dim3 avGrid(LL / 128, BH);                 // (16, 64)
    av_mma<<<avGrid, 256, PIPE_SMEM>>>(attn, vt, oc);

    gemm_proj<2><<<projGrid, 256, PIPE_SMEM>>>(oc, Wo, bo, out);
}